// round 1
// baseline (speedup 1.0000x reference)
#include <cuda_runtime.h>
#include <cstdint>

#define Bb 8
#define Cc 256
#define Nn 4096
#define Dd 16
#define BM 64
#define BN 32

// ---------------- scratch (static device arrays; no allocs) ----------------
__device__ float g_Q [(size_t)Bb * Nn * Dd];          // [B,N,D]
__device__ float g_K [(size_t)Bb * Dd * Nn];          // [B,D,N]
__device__ float g_VT[(size_t)Bb * Nn * Cc];          // [B,N,C]  (V transposed)
__device__ float g_OA[(size_t)Bb * Cc * Nn];          // [B,C,N]  attention output

// ---------------- packed f32x2 helpers ----------------
static __device__ __forceinline__ unsigned long long pack2(float x, float y) {
    unsigned long long r;
    asm("mov.b64 %0, {%1,%2};" : "=l"(r) : "f"(x), "f"(y));
    return r;
}
static __device__ __forceinline__ void unpack2(unsigned long long v, float &x, float &y) {
    asm("mov.b64 {%0,%1}, %2;" : "=f"(x), "=f"(y) : "l"(v));
}
static __device__ __forceinline__ void ffma2(unsigned long long &acc,
                                             unsigned long long a,
                                             unsigned long long b) {
    asm("fma.rn.f32x2 %0, %1, %2, %0;" : "+l"(acc) : "l"(a), "l"(b));
}
static __device__ __forceinline__ void fmul2(unsigned long long &a, unsigned long long b) {
    asm("mul.rn.f32x2 %0, %0, %1;" : "+l"(a) : "l"(b));
}

// ---------------- q/k projection: q=[B,N,D], k=[B,D,N] ----------------
__global__ __launch_bounds__(128) void qkproj_kernel(
    const float* __restrict__ x,
    const float* __restrict__ Wq, const float* __restrict__ bq,
    const float* __restrict__ Wk, const float* __restrict__ bk)
{
    __shared__ float wq[Dd * Cc];
    __shared__ float wk[Dd * Cc];
    int t = threadIdx.x;
    for (int i = t; i < Dd * Cc; i += 128) { wq[i] = Wq[i]; wk[i] = Wk[i]; }
    __syncthreads();

    int b = blockIdx.y;
    int n = blockIdx.x * 128 + t;

    float qa[Dd], ka[Dd];
#pragma unroll
    for (int d = 0; d < Dd; d++) { qa[d] = 0.f; ka[d] = 0.f; }

    const float* xp = x + (size_t)b * Cc * Nn + n;
#pragma unroll 4
    for (int c = 0; c < Cc; c++) {
        float xv = xp[(size_t)c * Nn];
#pragma unroll
        for (int d = 0; d < Dd; d++) {
            qa[d] += wq[d * Cc + c] * xv;
            ka[d] += wk[d * Cc + c] * xv;
        }
    }
    float* qo = g_Q + ((size_t)b * Nn + n) * Dd;
#pragma unroll
    for (int d = 0; d < Dd; d++) qo[d] = qa[d] + bq[d];
#pragma unroll
    for (int d = 0; d < Dd; d++) g_K[((size_t)b * Dd + d) * Nn + n] = ka[d] + bk[d];
}

// ---------------- V projection: VT[B,N,C] = (Wv @ x + bv)^T ----------------
__global__ __launch_bounds__(256) void vproj_kernel(
    const float* __restrict__ x,
    const float* __restrict__ Wv, const float* __restrict__ bv)
{
    __shared__ float Wt[64 * 65];
    __shared__ float Xt[64 * 65];
    int t  = threadIdx.x;
    int tr = t >> 4, tc = t & 15;
    int n0 = blockIdx.x * 64;
    int m0 = blockIdx.y * 64;
    int b  = blockIdx.z;

    float acc[4][4];
#pragma unroll
    for (int r = 0; r < 4; r++)
#pragma unroll
        for (int i = 0; i < 4; i++) acc[r][i] = 0.f;

    for (int kc = 0; kc < 4; kc++) {
        int k0 = kc * 64;
        __syncthreads();
#pragma unroll
        for (int l = 0; l < 16; l++) {
            int flat = t + l * 256;
            int rr = flat >> 6, kk = flat & 63;
            Wt[rr * 65 + kk] = Wv[(m0 + rr) * Cc + k0 + kk];
            Xt[rr * 65 + kk] = x[((size_t)(b * Cc + k0 + rr)) * Nn + n0 + kk];
        }
        __syncthreads();
#pragma unroll 8
        for (int kk = 0; kk < 64; kk++) {
            float av[4], bx[4];
#pragma unroll
            for (int r = 0; r < 4; r++) av[r] = Wt[(tr * 4 + r) * 65 + kk];
#pragma unroll
            for (int i = 0; i < 4; i++) bx[i] = Xt[kk * 65 + tc + 16 * i];
#pragma unroll
            for (int r = 0; r < 4; r++)
#pragma unroll
                for (int i = 0; i < 4; i++) acc[r][i] += av[r] * bx[i];
        }
    }
    float bias[4];
#pragma unroll
    for (int r = 0; r < 4; r++) bias[r] = bv[m0 + tr * 4 + r];

    // transpose through smem -> coalesced VT store
    __syncthreads();
#pragma unroll
    for (int r = 0; r < 4; r++)
#pragma unroll
        for (int i = 0; i < 4; i++)
            Wt[(tc + 16 * i) * 65 + tr * 4 + r] = acc[r][i] + bias[r];
    __syncthreads();
#pragma unroll
    for (int l = 0; l < 16; l++) {
        int flat = t + l * 256;
        int nl = flat >> 6, ml = flat & 63;
        g_VT[((size_t)(b * Nn + n0 + nl)) * Cc + m0 + ml] = Wt[nl * 65 + ml];
    }
}

// ---------------- fused flash attention: OA[B,C,N] ----------------
// smem carve (floats)
#define QS_OFF    0        // 64*17 = 1088
#define KS_OFF    1088     // 16*33 = 528
#define SS_OFF    1616     // 64*33 = 2112
#define VS_OFF    3728     // 32*258 = 8256  (8B aligned: 3728*4 = 14912)
#define RMAX_OFF  11984
#define RSUM_OFF  12048
#define RCORR_OFF 12112
#define SMEM_FLOATS 12176  // 48,704 B < 48 KB

__global__ __launch_bounds__(256, 2) void attn_kernel()
{
    __shared__ __align__(16) float S[SMEM_FLOATS];
    int t  = threadIdx.x;
    int tr = t >> 4, tc = t & 15;
    int b  = blockIdx.y;
    int m0 = blockIdx.x * BM;

    // load q tile [64,16]
#pragma unroll
    for (int l = 0; l < 4; l++) {
        int flat = t + l * 256;
        int m = flat >> 4, d = flat & 15;
        S[QS_OFF + m * 17 + d] = g_Q[((size_t)(b * Nn + m0 + m)) * Dd + d];
    }
    if (t < BM) { S[RMAX_OFF + t] = -1e30f; S[RSUM_OFF + t] = 0.f; }

    // o accumulators: 4 m-rows x 16 e (8 packed pairs), e = 2*tc + 32*i (+0/+1)
    unsigned long long o2[32];
#pragma unroll
    for (int i = 0; i < 32; i++) o2[i] = 0ull;

    const unsigned long long* vsd = reinterpret_cast<const unsigned long long*>(S + VS_OFF);
    float2* vs2 = reinterpret_cast<float2*>(S + VS_OFF);
    const float2* VT2 = reinterpret_cast<const float2*>(g_VT);

    for (int it = 0; it < Nn / BN; it++) {
        int n0 = it * BN;
        __syncthreads();
        // k tile [16,32]
#pragma unroll
        for (int l = 0; l < 2; l++) {
            int flat = t + l * 256;
            int d = flat >> 5, j = flat & 31;
            S[KS_OFF + d * 33 + j] = g_K[((size_t)(b * Dd + d)) * Nn + n0 + j];
        }
        // v tile [32,256] as float2, row stride 129 float2 (=258 floats)
#pragma unroll
        for (int l = 0; l < 16; l++) {
            int flat = t + l * 256;
            int j = flat >> 7, e2 = flat & 127;
            vs2[j * 129 + e2] = VT2[((size_t)(b * Nn + n0 + j)) * 128 + e2];
        }
        __syncthreads();

        // QK: s[m][j], m = tr*4+r, j = tc + 16*jj
        float sa[4][2];
#pragma unroll
        for (int r = 0; r < 4; r++) { sa[r][0] = 0.f; sa[r][1] = 0.f; }
#pragma unroll
        for (int d = 0; d < Dd; d++) {
            float k0v = S[KS_OFF + d * 33 + tc];
            float k1v = S[KS_OFF + d * 33 + tc + 16];
#pragma unroll
            for (int r = 0; r < 4; r++) {
                float qv = S[QS_OFF + (tr * 4 + r) * 17 + d];
                sa[r][0] += qv * k0v;
                sa[r][1] += qv * k1v;
            }
        }
#pragma unroll
        for (int r = 0; r < 4; r++)
#pragma unroll
            for (int jj = 0; jj < 2; jj++) {
                float s = 0.25f * sa[r][jj];               // scale = D^-0.5
                s = fminf(fmaxf(s, -50.f), 50.f);          // clip BEFORE softmax
                S[SS_OFF + (tr * 4 + r) * 33 + tc + 16 * jj] = s;
            }
        __syncthreads();

        // online softmax, one thread per row
        if (t < BM) {
            float om = S[RMAX_OFF + t];
            float tm = -1e30f;
#pragma unroll 8
            for (int j = 0; j < BN; j++) tm = fmaxf(tm, S[SS_OFF + t * 33 + j]);
            float nm = fmaxf(om, tm);
            float corr = __expf(om - nm);                  // first iter: exp(-inf)=0
            float sum = 0.f;
#pragma unroll 8
            for (int j = 0; j < BN; j++) {
                float p = __expf(S[SS_OFF + t * 33 + j] - nm);
                S[SS_OFF + t * 33 + j] = p;
                sum += p;
            }
            S[RSUM_OFF + t]  = S[RSUM_OFF + t] * corr + sum;
            S[RMAX_OFF + t]  = nm;
            S[RCORR_OFF + t] = corr;
        }
        __syncthreads();

        // rescale accumulators by corr
#pragma unroll
        for (int r = 0; r < 4; r++) {
            float c = S[RCORR_OFF + tr * 4 + r];
            unsigned long long c2 = pack2(c, c);
#pragma unroll
            for (int i = 0; i < 8; i++) fmul2(o2[r * 8 + i], c2);
        }
        // PV: o[m][e-pair] += p[m][j] * v[j][e-pair]   (packed FFMA2)
        for (int j = 0; j < BN; j++) {
            unsigned long long vv[8];
#pragma unroll
            for (int i = 0; i < 8; i++) vv[i] = vsd[j * 129 + tc + 16 * i];
            unsigned long long pv[4];
#pragma unroll
            for (int r = 0; r < 4; r++) {
                float p = S[SS_OFF + (tr * 4 + r) * 33 + j];
                pv[r] = pack2(p, p);
            }
#pragma unroll
            for (int r = 0; r < 4; r++)
#pragma unroll
                for (int i = 0; i < 8; i++)
                    ffma2(o2[r * 8 + i], pv[r], vv[i]);
        }
    }
    __syncthreads();

    float inv[4];
#pragma unroll
    for (int r = 0; r < 4; r++) inv[r] = 1.0f / S[RSUM_OFF + tr * 4 + r];

    // write OA[b][e][m0+..] transposed via smem staging, two e-halves of 128
    for (int h = 0; h < 2; h++) {
        __syncthreads();
#pragma unroll
        for (int r = 0; r < 4; r++)
#pragma unroll
            for (int i2 = 0; i2 < 4; i2++) {
                float lo, hi;
                unpack2(o2[r * 8 + h * 4 + i2], lo, hi);
                int le = 2 * tc + 32 * i2;
                S[le * 65 + tr * 4 + r]       = lo * inv[r];
                S[(le + 1) * 65 + tr * 4 + r] = hi * inv[r];
            }
        __syncthreads();
#pragma unroll
        for (int l = 0; l < 32; l++) {
            int flat = t + l * 256;
            int le = flat >> 6, ml = flat & 63;
            g_OA[((size_t)(b * Cc + h * 128 + le)) * Nn + m0 + ml] = S[le * 65 + ml];
        }
    }
}

// ---------------- output projection + residual: out = g*(Wo@OA + bo) + x ----------------
__global__ __launch_bounds__(256) void outproj_kernel(
    const float* __restrict__ x,
    const float* __restrict__ Wo, const float* __restrict__ bo,
    const float* __restrict__ gamma, float* __restrict__ out)
{
    __shared__ float Wt[64 * 65];
    __shared__ float Xt[64 * 65];
    int t  = threadIdx.x;
    int tr = t >> 4, tc = t & 15;
    int n0 = blockIdx.x * 64;
    int m0 = blockIdx.y * 64;
    int b  = blockIdx.z;

    float acc[4][4];
#pragma unroll
    for (int r = 0; r < 4; r++)
#pragma unroll
        for (int i = 0; i < 4; i++) acc[r][i] = 0.f;

    for (int kc = 0; kc < 4; kc++) {
        int k0 = kc * 64;
        __syncthreads();
#pragma unroll
        for (int l = 0; l < 16; l++) {
            int flat = t + l * 256;
            int rr = flat >> 6, kk = flat & 63;
            Wt[rr * 65 + kk] = Wo[(m0 + rr) * Cc + k0 + kk];
            Xt[rr * 65 + kk] = g_OA[((size_t)(b * Cc + k0 + rr)) * Nn + n0 + kk];
        }
        __syncthreads();
#pragma unroll 8
        for (int kk = 0; kk < 64; kk++) {
            float av[4], bx[4];
#pragma unroll
            for (int r = 0; r < 4; r++) av[r] = Wt[(tr * 4 + r) * 65 + kk];
#pragma unroll
            for (int i = 0; i < 4; i++) bx[i] = Xt[kk * 65 + tc + 16 * i];
#pragma unroll
            for (int r = 0; r < 4; r++)
#pragma unroll
                for (int i = 0; i < 4; i++) acc[r][i] += av[r] * bx[i];
        }
    }
    float g = fminf(fmaxf(gamma[0], 0.f), 1.f);
#pragma unroll
    for (int r = 0; r < 4; r++) {
        int m = m0 + tr * 4 + r;
        float bb = bo[m];
#pragma unroll
        for (int i = 0; i < 4; i++) {
            int n = n0 + tc + 16 * i;
            size_t idx = ((size_t)(b * Cc + m)) * Nn + n;
            out[idx] = g * (acc[r][i] + bb) + x[idx];
        }
    }
}

// ---------------- launcher ----------------
extern "C" void kernel_launch(void* const* d_in, const int* in_sizes, int n_in,
                              void* d_out, int out_size)
{
    const float* x     = (const float*)d_in[0];
    const float* Wq    = (const float*)d_in[1];
    const float* bq    = (const float*)d_in[2];
    const float* Wk    = (const float*)d_in[3];
    const float* bk    = (const float*)d_in[4];
    const float* Wv    = (const float*)d_in[5];
    const float* bv    = (const float*)d_in[6];
    const float* Wo    = (const float*)d_in[7];
    const float* bo    = (const float*)d_in[8];
    const float* gamma = (const float*)d_in[9];
    float* out = (float*)d_out;

    qkproj_kernel<<<dim3(Nn / 128, Bb), 128>>>(x, Wq, bq, Wk, bk);
    vproj_kernel <<<dim3(Nn / 64, Cc / 64, Bb), 256>>>(x, Wv, bv);
    attn_kernel  <<<dim3(Nn / BM, Bb), 256>>>();
    outproj_kernel<<<dim3(Nn / 64, Cc / 64, Bb), 256>>>(x, Wo, bo, gamma, out);
}